// round 13
// baseline (speedup 1.0000x reference)
#include <cuda_runtime.h>
#include <math_constants.h>

#define NROWS 4096
#define HALF_B 2048
#define DDIM 256
#define NT 512
#define IPT 8
#define NBUK 2048
#define BPT (NBUK / NT)   // buckets per thread in scans = 4
#define NWARP (NT / 32)

// Scratch (static device globals — no allocations anywhere)
__device__ float g_Fn[(size_t)NROWS * DDIM];          // normalized features, 4 MB
__device__ float g_logits[(size_t)NROWS * NROWS];     // logits matrix, 64 MB
__device__ float g_acc;                               // loss accumulator
__device__ unsigned g_done;                           // finished-block counter

struct RowSmem {
    float keyS[NROWS];     // bucket-scattered keys
    float expS[NROWS];     // bucket-scattered exps
    float histF[NBUK];     // exclusive per-bucket prefix P[b]
    int   offs[NBUK + 1];  // exclusive scan of counts
    int   cnt[NBUK];       // per-bucket counts (atomic returns within-idx)
    float redB[NWARP];
    float fwarp[NWARP];
    int   iwarp[NWARP];
    float bc[4];
};

// Packed dual-FMA: d = a * b + d, lanewise on 2x f32. Exactly fmaf per lane.
#define FFMA_F32X2(d, a, b) \
    asm("fma.rn.f32x2 %0, %1, %2, %0;" : "+l"(d) : "l"(a), "l"(b))

__device__ __forceinline__ int bucket_of(float q) {
    int b = (int)(q * (float)(NBUK / 4));   // key in [0,4]; q=-1 -> negative
    return (b > NBUK - 1) ? (NBUK - 1) : b;
}

// ---------------------------------------------------------------------------
// warp scan helpers
// ---------------------------------------------------------------------------
__device__ __forceinline__ int warp_incscan_i(int x, int lane) {
#pragma unroll
    for (int o = 1; o < 32; o <<= 1) {
        int y = __shfl_up_sync(0xffffffffu, x, o);
        if (lane >= o) x += y;
    }
    return x;
}
__device__ __forceinline__ float warp_incscan_f(float x, int lane) {
#pragma unroll
    for (int o = 1; o < 32; o <<= 1) {
        float y = __shfl_up_sync(0xffffffffu, x, o);
        if (lane >= o) x += y;
    }
    return x;
}

// ---------------------------------------------------------------------------
// Kernel 1: row-normalize concat([z_i; z_j]) -> g_Fn ; zero accumulators
// ---------------------------------------------------------------------------
__global__ void k_normalize(const float* __restrict__ zi, const float* __restrict__ zj) {
    int r = blockIdx.x;
    const float* src = (r < HALF_B) ? (zi + (size_t)r * DDIM)
                                    : (zj + (size_t)(r - HALF_B) * DDIM);
    int t = threadIdx.x;  // 64 threads, 4 floats each
    float4 v = reinterpret_cast<const float4*>(src)[t];
    float s = v.x * v.x + v.y * v.y + v.z * v.z + v.w * v.w;
#pragma unroll
    for (int o = 16; o; o >>= 1) s += __shfl_xor_sync(0xffffffffu, s, o);
    __shared__ float ws[2];
    if ((t & 31) == 0) ws[t >> 5] = s;
    __syncthreads();
    float inv = 1.0f / sqrtf(ws[0] + ws[1]);
    float4 o4 = make_float4(v.x * inv, v.y * inv, v.z * inv, v.w * inv);
    reinterpret_cast<float4*>(g_Fn + (size_t)r * DDIM)[t] = o4;
    if (r == 0 && t == 0) { g_acc = 0.0f; g_done = 0u; }
}

// ---------------------------------------------------------------------------
// Kernel 2: logits = (Fn @ Fn^T) * 0.5 — symmetric tiled GEMM, f32x2 FMAs
// ---------------------------------------------------------------------------
__global__ void __launch_bounds__(256) k_gemm() {
    int b = blockIdx.x;
    int by = (int)((sqrtf(8.0f * b + 1.0f) - 1.0f) * 0.5f);
    while ((by + 1) * (by + 2) / 2 <= b) by++;
    while (by * (by + 1) / 2 > b) by--;
    int bx = b - by * (by + 1) / 2;

    __shared__ float As[16][128];
    __shared__ float Bs[16][128];
    int tid = threadIdx.x;
    int tx = tid & 15, ty = tid >> 4;

    unsigned long long acc2[8][4];  // 8 rows x 4 f32x2 col-pairs
#pragma unroll
    for (int ii = 0; ii < 8; ii++)
#pragma unroll
        for (int jp = 0; jp < 4; jp++) acc2[ii][jp] = 0ULL;

    const float* A0 = g_Fn + (size_t)by * 128 * DDIM;
    const float* B0 = g_Fn + (size_t)bx * 128 * DDIM;

    for (int kt = 0; kt < DDIM; kt += 16) {
#pragma unroll
        for (int q = 0; q < 2; q++) {
            int slot = tid + q * 256;
            int r = slot >> 2;
            int c4 = (slot & 3) << 2;
            float4 va = *reinterpret_cast<const float4*>(A0 + (size_t)r * DDIM + kt + c4);
            As[c4 + 0][r] = va.x; As[c4 + 1][r] = va.y;
            As[c4 + 2][r] = va.z; As[c4 + 3][r] = va.w;
            float4 vb = *reinterpret_cast<const float4*>(B0 + (size_t)r * DDIM + kt + c4);
            Bs[c4 + 0][r] = vb.x; Bs[c4 + 1][r] = vb.y;
            Bs[c4 + 2][r] = vb.z; Bs[c4 + 3][r] = vb.w;
        }
        __syncthreads();
#pragma unroll
        for (int kk = 0; kk < 16; kk++) {
            float a[8];
            *reinterpret_cast<float4*>(a)     = *reinterpret_cast<float4*>(&As[kk][ty * 8]);
            *reinterpret_cast<float4*>(a + 4) = *reinterpret_cast<float4*>(&As[kk][ty * 8 + 4]);
            unsigned long long b2[4];
            const unsigned long long* bp =
                reinterpret_cast<const unsigned long long*>(&Bs[kk][tx * 8]);
            b2[0] = bp[0]; b2[1] = bp[1]; b2[2] = bp[2]; b2[3] = bp[3];
#pragma unroll
            for (int ii = 0; ii < 8; ii++) {
                unsigned long long a2;
                asm("mov.b64 %0, {%1, %1};" : "=l"(a2) : "r"(__float_as_uint(a[ii])));
#pragma unroll
                for (int jp = 0; jp < 4; jp++)
                    FFMA_F32X2(acc2[ii][jp], a2, b2[jp]);
            }
        }
        __syncthreads();
    }

    const float sc = 0.5f;  // 1 / TEMPERATURE
    int row0 = by * 128 + ty * 8;
    int col0 = bx * 128 + tx * 8;

    float accf[8][8];
#pragma unroll
    for (int ii = 0; ii < 8; ii++)
#pragma unroll
        for (int jp = 0; jp < 4; jp++) {
            accf[ii][2 * jp + 0] = __uint_as_float((unsigned)(acc2[ii][jp])) * sc;
            accf[ii][2 * jp + 1] = __uint_as_float((unsigned)(acc2[ii][jp] >> 32)) * sc;
        }

#pragma unroll
    for (int ii = 0; ii < 8; ii++) {
        float* dst = g_logits + (size_t)(row0 + ii) * NROWS + col0;
        *reinterpret_cast<float4*>(dst)     = *reinterpret_cast<float4*>(&accf[ii][0]);
        *reinterpret_cast<float4*>(dst + 4) = *reinterpret_cast<float4*>(&accf[ii][4]);
    }
    if (bx < by) {
#pragma unroll
        for (int jj = 0; jj < 8; jj++) {
            float4 w0 = make_float4(accf[0][jj], accf[1][jj], accf[2][jj], accf[3][jj]);
            float4 w1 = make_float4(accf[4][jj], accf[5][jj], accf[6][jj], accf[7][jj]);
            float* dst = g_logits + (size_t)(col0 + jj) * NROWS + row0;
            *reinterpret_cast<float4*>(dst)     = w0;
            *reinterpret_cast<float4*>(dst + 4) = w1;
        }
    }
}

// ---------------------------------------------------------------------------
// Kernel 3: per-row RnC reduction. ONE atomic/item; blocked pass-1 layout so
// logits load as 2x LDG.128 per thread (was 8x LDG.32).
// ---------------------------------------------------------------------------
__device__ __forceinline__ float4 ld_label(int r, const float* __restrict__ pi,
                                           const float* __restrict__ pj) {
    return (r < HALF_B) ? reinterpret_cast<const float4*>(pi)[r]
                        : reinterpret_cast<const float4*>(pj)[r - HALF_B];
}

__global__ void __launch_bounds__(NT) k_rows(const float* __restrict__ pi,
                                             const float* __restrict__ pj,
                                             float* __restrict__ out) {
    extern __shared__ char smem_raw[];
    RowSmem& S = *reinterpret_cast<RowSmem*>(smem_raw);
    const int i = blockIdx.x;
    const int t = threadIdx.x;
    const int lane = t & 31, wid = t >> 5;
    const float* Lrow = g_logits + (size_t)i * NROWS;

    const float mx = __ldg(Lrow + i);   // diagonal = row max (broadcast load)
    float4 li = ld_label(i, pi, pj);

    // zero bucket counts before count-phase atomics
#pragma unroll
    for (int k = 0; k < BPT; k++) S.cnt[t * BPT + k] = 0;
    __syncthreads();

    // --- Pass 1 (blocked j = t*IPT + k): 2x LDG.128 logits, 8x LDG.128 labels
    float vv[IPT];
    {
        const float4* L4 = reinterpret_cast<const float4*>(Lrow) + t * 2;
        float4 v0 = L4[0], v1 = L4[1];
        vv[0] = v0.x; vv[1] = v0.y; vv[2] = v0.z; vv[3] = v0.w;
        vv[4] = v1.x; vv[5] = v1.y; vv[6] = v1.z; vv[7] = v1.w;
    }
    float key[IPT], ex[IPT];
    int widx[IPT];
    float lsum = 0.f;
#pragma unroll
    for (int k = 0; k < IPT; k++) {
        int j = t * IPT + k;
        float v = vv[k];
        lsum += v;
        if (j == i) {
            key[k] = -1.f; ex[k] = 0.f; widx[k] = 0;   // diagonal sentinel
        } else {
            float4 lj = ld_label(j, pi, pj);
            float q = fabsf(li.x - lj.x) + fabsf(li.y - lj.y) +
                      fabsf(li.z - lj.z) + fabsf(li.w - lj.w);
            key[k] = q;
            ex[k] = __expf(v - mx);
            widx[k] = atomicAdd(&S.cnt[bucket_of(q)], 1);
        }
    }
#pragma unroll
    for (int o = 16; o; o >>= 1) lsum += __shfl_xor_sync(0xffffffffu, lsum, o);
    if (lane == 0) S.redB[wid] = lsum;
    __syncthreads();   // counts final + redB visible

    // --- exclusive int scan cnt -> offs; finish lsum ------------------------
    int iloc[BPT]; int irun = 0;
#pragma unroll
    for (int k = 0; k < BPT; k++) { iloc[k] = irun; irun += S.cnt[t * BPT + k]; }
    int iinc = warp_incscan_i(irun, lane);
    if (lane == 31) S.iwarp[wid] = iinc;
    __syncthreads();
    if (t < 32) {
        int v = (t < NWARP) ? S.iwarp[t] : 0;
        int vi = warp_incscan_i(v, t);
        if (t < NWARP) S.iwarp[t] = vi - v;
        float s = (t < NWARP) ? S.redB[t] : 0.f;
#pragma unroll
        for (int o = 8; o; o >>= 1) s += __shfl_xor_sync(0xffffffffu, s, o);
        if (t == 0) S.bc[1] = s;   // row logit sum
    }
    __syncthreads();
    int ibase = S.iwarp[wid] + (iinc - irun);
#pragma unroll
    for (int k = 0; k < BPT; k++) S.offs[t * BPT + k] = ibase + iloc[k];
    if (t == 0) S.offs[NBUK] = NROWS - 1;
    __syncthreads();

    // --- scatter: plain stores at offs[b] + widx -----------------------------
#pragma unroll
    for (int k = 0; k < IPT; k++) {
        if (key[k] >= 0.f) {
            int p = S.offs[bucket_of(key[k])] + widx[k];
            S.keyS[p] = key[k];
            S.expS[p] = ex[k];
        }
    }
    __syncthreads();

    // --- per-bucket exp sums from expS (owner thread), then float scan ------
    float floc[BPT]; float frun = 0.f;
#pragma unroll
    for (int k = 0; k < BPT; k++) {
        int b = t * BPT + k;
        int lo = S.offs[b], hi = S.offs[b + 1];
        float s = 0.f;
        for (int idx = lo; idx < hi; ++idx) s += S.expS[idx];
        floc[k] = frun;
        frun += s;
    }
    float finc = warp_incscan_f(frun, lane);
    if (lane == 31) S.fwarp[wid] = finc;
    __syncthreads();
    if (t < 32) {
        float f = (t < NWARP) ? S.fwarp[t] : 0.f;
        float fi = warp_incscan_f(f, t);
        if (t < NWARP) S.fwarp[t] = fi - f;
        if (t == NWARP - 1) S.bc[2] = fi;   // grand total of exps
    }
    __syncthreads();
    float fbase = S.fwarp[wid] + (finc - frun);
#pragma unroll
    for (int k = 0; k < BPT; k++)
        S.histF[t * BPT + k] = fbase + floc[k];   // P[b], exclusive
    __syncthreads();

    const float total = S.bc[2];
    const float sumL = S.bc[1];

    // --- pass B: below = P[b] + strictly-smaller-in-bucket; accumulate log --
    float acc = 0.f;
#pragma unroll
    for (int k = 0; k < IPT; k++) {
        float q = key[k];
        if (q < 0.f) continue;
        int b = bucket_of(q);
        float below = S.histF[b];
        int lo = S.offs[b], hi = S.offs[b + 1];
        if (hi - lo > 1) {   // singleton bucket: below = P[b], skip LDS loop
            for (int idx = lo; idx < hi; ++idx) {
                if (S.keyS[idx] < q) below += S.expS[idx];
            }
        }
        acc += __logf(total - below + 1e-8f);
    }
#pragma unroll
    for (int o = 16; o; o >>= 1) acc += __shfl_xor_sync(0xffffffffu, acc, o);
    if (lane == 0) S.redB[wid] = acc;
    __syncthreads();
    if (t < 32) {
        float s = (t < NWARP) ? S.redB[t] : 0.f;
#pragma unroll
        for (int o = 8; o; o >>= 1) s += __shfl_xor_sync(0xffffffffu, s, o);
        if (t == 0) {
            float sum_logits_o = (sumL - mx) - (float)(NROWS - 1) * mx;
            atomicAdd(&g_acc, sum_logits_o - s);
            __threadfence();
            unsigned old = atomicAdd(&g_done, 1u);
            if (old == NROWS - 1) {
                float a = atomicAdd(&g_acc, 0.0f);  // coherent read of final sum
                out[0] = -a / 16773120.0f;          // n*(n-1) = 4096*4095
            }
        }
    }
}

// ---------------------------------------------------------------------------
extern "C" void kernel_launch(void* const* d_in, const int* in_sizes, int n_in,
                              void* d_out, int out_size) {
    const float* zi = (const float*)d_in[0];
    const float* zj = (const float*)d_in[1];
    const float* pi = (const float*)d_in[2];
    const float* pj = (const float*)d_in[3];
    float* out = (float*)d_out;

    static bool attr_set = false;
    if (!attr_set) {
        cudaFuncSetAttribute((const void*)k_rows,
                             cudaFuncAttributeMaxDynamicSharedMemorySize,
                             (int)sizeof(RowSmem));
        attr_set = true;
    }

    k_normalize<<<NROWS, 64>>>(zi, zj);
    k_gemm<<<32 * 33 / 2, 256>>>();
    k_rows<<<NROWS, NT, sizeof(RowSmem)>>>(pi, pj, out);
}

// round 14
// speedup vs baseline: 1.1741x; 1.1741x over previous
#include <cuda_runtime.h>
#include <math_constants.h>

#define NROWS 4096
#define HALF_B 2048
#define DDIM 256
#define NT 512
#define IPT 8
#define NBUK 2048
#define BPT (NBUK / NT)   // buckets per thread in scans = 4
#define NWARP (NT / 32)

// Scratch (static device globals — no allocations anywhere)
__device__ float g_Fn[(size_t)NROWS * DDIM];          // normalized features, 4 MB
__device__ float g_logits[(size_t)NROWS * NROWS];     // logits matrix, 64 MB
__device__ float g_acc;                               // loss accumulator
__device__ unsigned g_done;                           // finished-block counter

struct RowSmem {
    float keyS[NROWS];     // bucket-scattered keys
    float expS[NROWS];     // bucket-scattered exps
    float histF[NBUK];     // exclusive per-bucket prefix P[b]
    int   offs[NBUK + 1];  // exclusive scan of counts
    int   cnt[NBUK];       // per-bucket counts (atomic returns within-idx)
    float redB[NWARP];
    float fwarp[NWARP];
    int   iwarp[NWARP];
    float bc[4];
};

// Packed dual-FMA: d = a * b + d, lanewise on 2x f32. Exactly fmaf per lane.
#define FFMA_F32X2(d, a, b) \
    asm("fma.rn.f32x2 %0, %1, %2, %0;" : "+l"(d) : "l"(a), "l"(b))

__device__ __forceinline__ int bucket_of(float q) {
    int b = (int)(q * (float)(NBUK / 4));   // key in [0,4]; q=-1 -> negative
    return (b > NBUK - 1) ? (NBUK - 1) : b;
}

// ---------------------------------------------------------------------------
// warp scan helpers
// ---------------------------------------------------------------------------
__device__ __forceinline__ int warp_incscan_i(int x, int lane) {
#pragma unroll
    for (int o = 1; o < 32; o <<= 1) {
        int y = __shfl_up_sync(0xffffffffu, x, o);
        if (lane >= o) x += y;
    }
    return x;
}
__device__ __forceinline__ float warp_incscan_f(float x, int lane) {
#pragma unroll
    for (int o = 1; o < 32; o <<= 1) {
        float y = __shfl_up_sync(0xffffffffu, x, o);
        if (lane >= o) x += y;
    }
    return x;
}

// ---------------------------------------------------------------------------
// Kernel 1: row-normalize concat([z_i; z_j]) -> g_Fn ; zero accumulators
// ---------------------------------------------------------------------------
__global__ void k_normalize(const float* __restrict__ zi, const float* __restrict__ zj) {
    int r = blockIdx.x;
    const float* src = (r < HALF_B) ? (zi + (size_t)r * DDIM)
                                    : (zj + (size_t)(r - HALF_B) * DDIM);
    int t = threadIdx.x;  // 64 threads, 4 floats each
    float4 v = reinterpret_cast<const float4*>(src)[t];
    float s = v.x * v.x + v.y * v.y + v.z * v.z + v.w * v.w;
#pragma unroll
    for (int o = 16; o; o >>= 1) s += __shfl_xor_sync(0xffffffffu, s, o);
    __shared__ float ws[2];
    if ((t & 31) == 0) ws[t >> 5] = s;
    __syncthreads();
    float inv = 1.0f / sqrtf(ws[0] + ws[1]);
    float4 o4 = make_float4(v.x * inv, v.y * inv, v.z * inv, v.w * inv);
    reinterpret_cast<float4*>(g_Fn + (size_t)r * DDIM)[t] = o4;
    if (r == 0 && t == 0) { g_acc = 0.0f; g_done = 0u; }
}

// ---------------------------------------------------------------------------
// Kernel 2: logits = (Fn @ Fn^T) * 0.5 — symmetric tiled GEMM, f32x2 FMAs
// ---------------------------------------------------------------------------
__global__ void __launch_bounds__(256) k_gemm() {
    int b = blockIdx.x;
    int by = (int)((sqrtf(8.0f * b + 1.0f) - 1.0f) * 0.5f);
    while ((by + 1) * (by + 2) / 2 <= b) by++;
    while (by * (by + 1) / 2 > b) by--;
    int bx = b - by * (by + 1) / 2;

    __shared__ float As[16][128];
    __shared__ float Bs[16][128];
    int tid = threadIdx.x;
    int tx = tid & 15, ty = tid >> 4;

    unsigned long long acc2[8][4];  // 8 rows x 4 f32x2 col-pairs
#pragma unroll
    for (int ii = 0; ii < 8; ii++)
#pragma unroll
        for (int jp = 0; jp < 4; jp++) acc2[ii][jp] = 0ULL;

    const float* A0 = g_Fn + (size_t)by * 128 * DDIM;
    const float* B0 = g_Fn + (size_t)bx * 128 * DDIM;

    for (int kt = 0; kt < DDIM; kt += 16) {
#pragma unroll
        for (int q = 0; q < 2; q++) {
            int slot = tid + q * 256;
            int r = slot >> 2;
            int c4 = (slot & 3) << 2;
            float4 va = *reinterpret_cast<const float4*>(A0 + (size_t)r * DDIM + kt + c4);
            As[c4 + 0][r] = va.x; As[c4 + 1][r] = va.y;
            As[c4 + 2][r] = va.z; As[c4 + 3][r] = va.w;
            float4 vb = *reinterpret_cast<const float4*>(B0 + (size_t)r * DDIM + kt + c4);
            Bs[c4 + 0][r] = vb.x; Bs[c4 + 1][r] = vb.y;
            Bs[c4 + 2][r] = vb.z; Bs[c4 + 3][r] = vb.w;
        }
        __syncthreads();
#pragma unroll
        for (int kk = 0; kk < 16; kk++) {
            float a[8];
            *reinterpret_cast<float4*>(a)     = *reinterpret_cast<float4*>(&As[kk][ty * 8]);
            *reinterpret_cast<float4*>(a + 4) = *reinterpret_cast<float4*>(&As[kk][ty * 8 + 4]);
            unsigned long long b2[4];
            const unsigned long long* bp =
                reinterpret_cast<const unsigned long long*>(&Bs[kk][tx * 8]);
            b2[0] = bp[0]; b2[1] = bp[1]; b2[2] = bp[2]; b2[3] = bp[3];
#pragma unroll
            for (int ii = 0; ii < 8; ii++) {
                unsigned long long a2;
                asm("mov.b64 %0, {%1, %1};" : "=l"(a2) : "r"(__float_as_uint(a[ii])));
#pragma unroll
                for (int jp = 0; jp < 4; jp++)
                    FFMA_F32X2(acc2[ii][jp], a2, b2[jp]);
            }
        }
        __syncthreads();
    }

    const float sc = 0.5f;  // 1 / TEMPERATURE
    int row0 = by * 128 + ty * 8;
    int col0 = bx * 128 + tx * 8;

    float accf[8][8];
#pragma unroll
    for (int ii = 0; ii < 8; ii++)
#pragma unroll
        for (int jp = 0; jp < 4; jp++) {
            accf[ii][2 * jp + 0] = __uint_as_float((unsigned)(acc2[ii][jp])) * sc;
            accf[ii][2 * jp + 1] = __uint_as_float((unsigned)(acc2[ii][jp] >> 32)) * sc;
        }

#pragma unroll
    for (int ii = 0; ii < 8; ii++) {
        float* dst = g_logits + (size_t)(row0 + ii) * NROWS + col0;
        *reinterpret_cast<float4*>(dst)     = *reinterpret_cast<float4*>(&accf[ii][0]);
        *reinterpret_cast<float4*>(dst + 4) = *reinterpret_cast<float4*>(&accf[ii][4]);
    }
    if (bx < by) {
#pragma unroll
        for (int jj = 0; jj < 8; jj++) {
            float4 w0 = make_float4(accf[0][jj], accf[1][jj], accf[2][jj], accf[3][jj]);
            float4 w1 = make_float4(accf[4][jj], accf[5][jj], accf[6][jj], accf[7][jj]);
            float* dst = g_logits + (size_t)(col0 + jj) * NROWS + row0;
            *reinterpret_cast<float4*>(dst)     = w0;
            *reinterpret_cast<float4*>(dst + 4) = w1;
        }
    }
}

// ---------------------------------------------------------------------------
// Kernel 3: per-row RnC reduction. ONE atomic/item, STRIDED pass-1 layout
// (coalesced: lanes access consecutive j at each unrolled step).
// ---------------------------------------------------------------------------
__device__ __forceinline__ float4 ld_label(int r, const float* __restrict__ pi,
                                           const float* __restrict__ pj) {
    return (r < HALF_B) ? reinterpret_cast<const float4*>(pi)[r]
                        : reinterpret_cast<const float4*>(pj)[r - HALF_B];
}

__global__ void __launch_bounds__(NT) k_rows(const float* __restrict__ pi,
                                             const float* __restrict__ pj,
                                             float* __restrict__ out) {
    extern __shared__ char smem_raw[];
    RowSmem& S = *reinterpret_cast<RowSmem*>(smem_raw);
    const int i = blockIdx.x;
    const int t = threadIdx.x;
    const int lane = t & 31, wid = t >> 5;
    const float* Lrow = g_logits + (size_t)i * NROWS;

    const float mx = __ldg(Lrow + i);   // diagonal = row max (broadcast load)
    float4 li = ld_label(i, pi, pj);

    // zero bucket counts before count-phase atomics
#pragma unroll
    for (int k = 0; k < BPT; k++) S.cnt[t * BPT + k] = 0;
    __syncthreads();

    // --- Pass 1 (strided j = t + k*NT): coalesced logit + label loads -------
    float key[IPT], ex[IPT];
    int widx[IPT];
    float lsum = 0.f;
#pragma unroll
    for (int k = 0; k < IPT; k++) {
        int j = t + k * NT;
        float v = Lrow[j];
        lsum += v;
        if (j == i) {
            key[k] = -1.f; ex[k] = 0.f; widx[k] = 0;   // diagonal sentinel
        } else {
            float4 lj = ld_label(j, pi, pj);
            float q = fabsf(li.x - lj.x) + fabsf(li.y - lj.y) +
                      fabsf(li.z - lj.z) + fabsf(li.w - lj.w);
            key[k] = q;
            ex[k] = __expf(v - mx);
            widx[k] = atomicAdd(&S.cnt[bucket_of(q)], 1);
        }
    }
#pragma unroll
    for (int o = 16; o; o >>= 1) lsum += __shfl_xor_sync(0xffffffffu, lsum, o);
    if (lane == 0) S.redB[wid] = lsum;
    __syncthreads();   // counts final + redB visible

    // --- exclusive int scan cnt -> offs; finish lsum ------------------------
    int iloc[BPT]; int irun = 0;
#pragma unroll
    for (int k = 0; k < BPT; k++) { iloc[k] = irun; irun += S.cnt[t * BPT + k]; }
    int iinc = warp_incscan_i(irun, lane);
    if (lane == 31) S.iwarp[wid] = iinc;
    __syncthreads();
    if (t < 32) {
        int v = (t < NWARP) ? S.iwarp[t] : 0;
        int vi = warp_incscan_i(v, t);
        if (t < NWARP) S.iwarp[t] = vi - v;
        float s = (t < NWARP) ? S.redB[t] : 0.f;
#pragma unroll
        for (int o = 8; o; o >>= 1) s += __shfl_xor_sync(0xffffffffu, s, o);
        if (t == 0) S.bc[1] = s;   // row logit sum
    }
    __syncthreads();
    int ibase = S.iwarp[wid] + (iinc - irun);
#pragma unroll
    for (int k = 0; k < BPT; k++) S.offs[t * BPT + k] = ibase + iloc[k];
    if (t == 0) S.offs[NBUK] = NROWS - 1;
    __syncthreads();

    // --- scatter: plain stores at offs[b] + widx -----------------------------
#pragma unroll
    for (int k = 0; k < IPT; k++) {
        if (key[k] >= 0.f) {
            int p = S.offs[bucket_of(key[k])] + widx[k];
            S.keyS[p] = key[k];
            S.expS[p] = ex[k];
        }
    }
    __syncthreads();

    // --- per-bucket exp sums from expS (owner thread), then float scan ------
    float floc[BPT]; float frun = 0.f;
#pragma unroll
    for (int k = 0; k < BPT; k++) {
        int b = t * BPT + k;
        int lo = S.offs[b], hi = S.offs[b + 1];
        float s = 0.f;
        for (int idx = lo; idx < hi; ++idx) s += S.expS[idx];
        floc[k] = frun;
        frun += s;
    }
    float finc = warp_incscan_f(frun, lane);
    if (lane == 31) S.fwarp[wid] = finc;
    __syncthreads();
    if (t < 32) {
        float f = (t < NWARP) ? S.fwarp[t] : 0.f;
        float fi = warp_incscan_f(f, t);
        if (t < NWARP) S.fwarp[t] = fi - f;
        if (t == NWARP - 1) S.bc[2] = fi;   // grand total of exps
    }
    __syncthreads();
    float fbase = S.fwarp[wid] + (finc - frun);
#pragma unroll
    for (int k = 0; k < BPT; k++)
        S.histF[t * BPT + k] = fbase + floc[k];   // P[b], exclusive
    __syncthreads();

    const float total = S.bc[2];
    const float sumL = S.bc[1];

    // --- pass B: below = P[b] + strictly-smaller-in-bucket; accumulate log --
    float acc = 0.f;
#pragma unroll
    for (int k = 0; k < IPT; k++) {
        float q = key[k];
        if (q < 0.f) continue;
        int b = bucket_of(q);
        float below = S.histF[b];
        int lo = S.offs[b], hi = S.offs[b + 1];
        if (hi - lo > 1) {   // singleton bucket: below = P[b], skip LDS loop
            for (int idx = lo; idx < hi; ++idx) {
                if (S.keyS[idx] < q) below += S.expS[idx];
            }
        }
        acc += __logf(total - below + 1e-8f);
    }
#pragma unroll
    for (int o = 16; o; o >>= 1) acc += __shfl_xor_sync(0xffffffffu, acc, o);
    if (lane == 0) S.redB[wid] = acc;
    __syncthreads();
    if (t < 32) {
        float s = (t < NWARP) ? S.redB[t] : 0.f;
#pragma unroll
        for (int o = 8; o; o >>= 1) s += __shfl_xor_sync(0xffffffffu, s, o);
        if (t == 0) {
            float sum_logits_o = (sumL - mx) - (float)(NROWS - 1) * mx;
            atomicAdd(&g_acc, sum_logits_o - s);
            __threadfence();
            unsigned old = atomicAdd(&g_done, 1u);
            if (old == NROWS - 1) {
                float a = atomicAdd(&g_acc, 0.0f);  // coherent read of final sum
                out[0] = -a / 16773120.0f;          // n*(n-1) = 4096*4095
            }
        }
    }
}

// ---------------------------------------------------------------------------
extern "C" void kernel_launch(void* const* d_in, const int* in_sizes, int n_in,
                              void* d_out, int out_size) {
    const float* zi = (const float*)d_in[0];
    const float* zj = (const float*)d_in[1];
    const float* pi = (const float*)d_in[2];
    const float* pj = (const float*)d_in[3];
    float* out = (float*)d_out;

    static bool attr_set = false;
    if (!attr_set) {
        cudaFuncSetAttribute((const void*)k_rows,
                             cudaFuncAttributeMaxDynamicSharedMemorySize,
                             (int)sizeof(RowSmem));
        attr_set = true;
    }

    k_normalize<<<NROWS, 64>>>(zi, zj);
    k_gemm<<<32 * 33 / 2, 256>>>();
    k_rows<<<NROWS, NT, sizeof(RowSmem)>>>(pi, pj, out);
}